// round 15
// baseline (speedup 1.0000x reference)
#include <cuda_runtime.h>
#include <cuda_bf16.h>
#include <cuda_fp16.h>
#include <cstdint>

#define N_PIX 4096
#define BATCH 4
#define CH    256
#define DQK   32

typedef unsigned long long u64;
typedef unsigned int u32;

// ---------------- scratch (device globals) ------------------------------------------
__device__ __half g_qf[(size_t)BATCH * N_PIX * DQK];  // Q fp16 [b][n][32]
__device__ __half g_kf[(size_t)BATCH * N_PIX * DQK];  // K fp16 [b][m][32]
__device__ __half g_vf[(size_t)BATCH * CH * N_PIX];   // V fp16 [b][d][m]

// ---------------- f32x2 helpers ------------------------------------------------------
__device__ __forceinline__ u64 fma2(u64 a, u64 b, u64 c) {
    u64 d;
    asm("fma.rn.f32x2 %0, %1, %2, %3;" : "=l"(d) : "l"(a), "l"(b), "l"(c));
    return d;
}
__device__ __forceinline__ u64 pack2(float x, float y) {
    u64 r;
    asm("mov.b64 %0, {%1, %2};" : "=l"(r) : "f"(x), "f"(y));
    return r;
}
__device__ __forceinline__ float2 unpack2(u64 v) {
    float2 r;
    asm("mov.b64 {%0, %1}, %2;" : "=f"(r.x), "=f"(r.y) : "l"(v));
    return r;
}

// ---------------- split-bf16 helper (V projection inputs) ----------------------------
__device__ __forceinline__ void split2(float a, float b, u32& hi, u32& lo) {
    __nv_bfloat162 h = __floats2bfloat162_rn(a, b);
    u32 hraw = *(const u32*)&h;
    float ha = __uint_as_float(hraw << 16);
    float hb = __uint_as_float(hraw & 0xFFFF0000u);
    __nv_bfloat162 l = __floats2bfloat162_rn(a - ha, b - hb);
    hi = hraw;
    lo = *(const u32*)&l;
}

// ---------------- smem / cp.async / mma helpers -------------------------------------
__device__ __forceinline__ u32 smem_u32(const void* p) {
    u32 a;
    asm("{ .reg .u64 t; cvta.to.shared.u64 t, %1; cvt.u32.u64 %0, t; }" : "=r"(a) : "l"(p));
    return a;
}
__device__ __forceinline__ void cp16(u32 d, const void* s) {
    asm volatile("cp.async.cg.shared.global [%0], [%1], 16;" :: "r"(d), "l"(s));
}
#define CP_COMMIT() asm volatile("cp.async.commit_group;" ::: "memory")
#define CP_WAIT2()  asm volatile("cp.async.wait_group 2;" ::: "memory")
#define CP_WAIT1()  asm volatile("cp.async.wait_group 1;" ::: "memory")
#define CP_WAIT0()  asm volatile("cp.async.wait_group 0;" ::: "memory")

__device__ __forceinline__ void ldm4(u32 addr, u32& r0, u32& r1, u32& r2, u32& r3) {
    asm volatile("ldmatrix.sync.aligned.m8n8.x4.shared.b16 {%0,%1,%2,%3}, [%4];"
                 : "=r"(r0), "=r"(r1), "=r"(r2), "=r"(r3) : "r"(addr));
}
__device__ __forceinline__ void ldm4t(u32 addr, u32& r0, u32& r1, u32& r2, u32& r3) {
    asm volatile("ldmatrix.sync.aligned.m8n8.x4.trans.shared.b16 {%0,%1,%2,%3}, [%4];"
                 : "=r"(r0), "=r"(r1), "=r"(r2), "=r"(r3) : "r"(addr));
}
// bf16 MMA (V projection)
__device__ __forceinline__ void mma16816(float* c, const u32* a, u32 b0, u32 b1) {
    asm volatile(
        "mma.sync.aligned.m16n8k16.row.col.f32.bf16.bf16.f32 "
        "{%0,%1,%2,%3}, {%4,%5,%6,%7}, {%8,%9}, {%0,%1,%2,%3};"
        : "+f"(c[0]), "+f"(c[1]), "+f"(c[2]), "+f"(c[3])
        : "r"(a[0]), "r"(a[1]), "r"(a[2]), "r"(a[3]), "r"(b0), "r"(b1));
}
// fp16 MMA (E + PV)
__device__ __forceinline__ void mma16816h(float* c, const u32* a, u32 b0, u32 b1) {
    asm volatile(
        "mma.sync.aligned.m16n8k16.row.col.f32.f16.f16.f32 "
        "{%0,%1,%2,%3}, {%4,%5,%6,%7}, {%8,%9}, {%0,%1,%2,%3};"
        : "+f"(c[0]), "+f"(c[1]), "+f"(c[2]), "+f"(c[3])
        : "r"(a[0]), "r"(a[1]), "r"(a[2]), "r"(a[3]), "r"(b0), "r"(b1));
}
__device__ __forceinline__ u32 ex2h2(u32 z) {
    asm("ex2.approx.f16x2 %0, %0;" : "+r"(z));
    return z;
}

// ================== fat projection kernel ==========================================
#define PROJ_SMEM 38400

__global__ void __launch_bounds__(256, 2) proj_fused_kernel(
    const float* __restrict__ x,
    const float* __restrict__ Wq, const float* __restrict__ bq,
    const float* __restrict__ Wk, const float* __restrict__ bk,
    const float* __restrict__ Wv, const float* __restrict__ bv)
{
    extern __shared__ char psm[];
    const int tid = threadIdx.x;
    const int b = blockIdx.y;

    if (blockIdx.x < 32) {
        float* sX = (float*)psm;
        float* sW = (float*)(psm + 16896);

        const int g = tid & 31;
        const int h = tid >> 5;
        const int n0 = blockIdx.x * 128;
        const bool isq = (h < 4);
        const int dbase = (h & 3) * 8;
        const int woff = (isq ? 0 : 32) + dbase;

        u64 acc[8][2];
#pragma unroll
        for (int i = 0; i < 8; i++) { acc[i][0] = 0; acc[i][1] = 0; }

        for (int c0 = 0; c0 < CH; c0 += 32) {
            __syncthreads();
#pragma unroll
            for (int pass = 0; pass < 4; ++pass) {
                int cc = h + pass * 8;
                const float* src = x + ((size_t)b * CH + c0 + cc) * N_PIX + n0 + g * 4;
                *(float4*)(sX + cc * 132 + g * 4) = *(const float4*)src;
            }
            {
                int d = tid & 31;
                int c4 = (tid >> 5) * 4;
                float4 wq4 = *(const float4*)(Wq + d * CH + c0 + c4);
                float4 wk4 = *(const float4*)(Wk + d * CH + c0 + c4);
                sW[(c4 + 0) * 68 + d] = wq4.x; sW[(c4 + 1) * 68 + d] = wq4.y;
                sW[(c4 + 2) * 68 + d] = wq4.z; sW[(c4 + 3) * 68 + d] = wq4.w;
                sW[(c4 + 0) * 68 + 32 + d] = wk4.x; sW[(c4 + 1) * 68 + 32 + d] = wk4.y;
                sW[(c4 + 2) * 68 + 32 + d] = wk4.z; sW[(c4 + 3) * 68 + 32 + d] = wk4.w;
            }
            __syncthreads();

#pragma unroll 8
            for (int cc = 0; cc < 32; ++cc) {
                float4 xa = *(const float4*)(sX + cc * 132 + g * 4);
                u64 xp0 = pack2(xa.x, xa.y), xp1 = pack2(xa.z, xa.w);
                const float* wp = sW + cc * 68 + woff;
                float4 w0 = *(const float4*)wp;
                float4 w1 = *(const float4*)(wp + 4);
                float wv[8] = {w0.x, w0.y, w0.z, w0.w, w1.x, w1.y, w1.z, w1.w};
#pragma unroll
                for (int i = 0; i < 8; i++) {
                    u64 wd = pack2(wv[i], wv[i]);
                    acc[i][0] = fma2(wd, xp0, acc[i][0]);
                    acc[i][1] = fma2(wd, xp1, acc[i][1]);
                }
            }
        }

        const float* bias = isq ? bq : bk;
        float bb[8];
#pragma unroll
        for (int i = 0; i < 8; i++) bb[i] = bias[dbase + i];
        __half* oq = (isq ? g_qf : g_kf)
                     + ((size_t)b * N_PIX + n0 + g * 4) * DQK + dbase;
#pragma unroll
        for (int j = 0; j < 4; j++) {
            float v[8];
#pragma unroll
            for (int i = 0; i < 8; i++) {
                float2 t = unpack2(acc[i][j >> 1]);
                v[i] = ((j & 1) ? t.y : t.x) + bb[i];
            }
            __half2 p0 = __floats2half2_rn(v[0], v[1]);
            __half2 p1 = __floats2half2_rn(v[2], v[3]);
            __half2 p2 = __floats2half2_rn(v[4], v[5]);
            __half2 p3 = __floats2half2_rn(v[6], v[7]);
            uint4 u = make_uint4(*(const u32*)&p0, *(const u32*)&p1,
                                 *(const u32*)&p2, *(const u32*)&p3);
            *(uint4*)(oq + (size_t)j * DQK) = u;
        }
    } else {
        __nv_bfloat16* sWh = (__nv_bfloat16*)psm;
        __nv_bfloat16* sWl = (__nv_bfloat16*)(psm + 10240);
        __nv_bfloat16* sXh = (__nv_bfloat16*)(psm + 20480);
        __nv_bfloat16* sXl = (__nv_bfloat16*)(psm + 29184);

        const int w = tid >> 5, lane = tid & 31;
        const int idx0 = blockIdx.x - 32;
        const int d0 = (idx0 >> 5) * 128;
        const int m0 = (idx0 & 31) * 128;

        float accV[16][4];
#pragma unroll
        for (int i = 0; i < 16; i++)
#pragma unroll
            for (int q = 0; q < 4; q++) accV[i][q] = 0.f;

        const int arow = w * 16 + (lane & 15);
        const int acol = (lane >> 4) << 3;
        const int brow_c = (lane & 7) + ((lane >> 3) & 1) * 8;
        const int bcol_m = ((lane >> 4) & 1) * 8;

        const u32 SWH = smem_u32(sWh), SWL = smem_u32(sWl);
        const u32 SXH = smem_u32(sXh), SXL = smem_u32(sXl);

        for (int c0 = 0; c0 < CH; c0 += 32) {
            __syncthreads();
#pragma unroll
            for (int j = 0; j < 4; j++) {
                int idx = tid + j * 256;
                int d = idx >> 3, c4 = (idx & 7) * 4;
                float4 wv4 = *(const float4*)(Wv + (size_t)(d0 + d) * CH + c0 + c4);
                u32 h0, l0, h1, l1;
                split2(wv4.x, wv4.y, h0, l0);
                split2(wv4.z, wv4.w, h1, l1);
                *(uint2*)&sWh[d * 40 + c4] = make_uint2(h0, h1);
                *(uint2*)&sWl[d * 40 + c4] = make_uint2(l0, l1);
            }
#pragma unroll
            for (int j = 0; j < 4; j++) {
                int idx = tid + j * 256;
                int c = idx >> 5, m4 = (idx & 31) * 4;
                float4 xv4 = *(const float4*)(x + ((size_t)b * CH + c0 + c) * N_PIX + m0 + m4);
                u32 h0, l0, h1, l1;
                split2(xv4.x, xv4.y, h0, l0);
                split2(xv4.z, xv4.w, h1, l1);
                *(uint2*)&sXh[c * 136 + m4] = make_uint2(h0, h1);
                *(uint2*)&sXl[c * 136 + m4] = make_uint2(l0, l1);
            }
            __syncthreads();

#pragma unroll
            for (int kk = 0; kk < 32; kk += 16) {
                u32 ah[4], al[4];
                u32 ao = (u32)(arow * 40 + acol + kk) * 2;
                ldm4(SWH + ao, ah[0], ah[1], ah[2], ah[3]);
                ldm4(SWL + ao, al[0], al[1], al[2], al[3]);
#pragma unroll
                for (int mb = 0; mb < 8; mb++) {
                    u32 boff = (u32)((kk + brow_c) * 136 + mb * 16 + bcol_m) * 2;
                    u32 bh[4], bl[4];
                    ldm4t(SXH + boff, bh[0], bh[1], bh[2], bh[3]);
                    ldm4t(SXL + boff, bl[0], bl[1], bl[2], bl[3]);
                    mma16816(accV[mb * 2],     ah, bh[0], bh[1]);
                    mma16816(accV[mb * 2],     ah, bl[0], bl[1]);
                    mma16816(accV[mb * 2],     al, bh[0], bh[1]);
                    mma16816(accV[mb * 2 + 1], ah, bh[2], bh[3]);
                    mma16816(accV[mb * 2 + 1], ah, bl[2], bl[3]);
                    mma16816(accV[mb * 2 + 1], al, bh[2], bh[3]);
                }
            }
        }

        const int er = lane >> 2, ec = 2 * (lane & 3);
        const int dA = d0 + w * 16 + er;
        const int dB = dA + 8;
        const float biasA = bv[dA], biasB = bv[dB];
#pragma unroll
        for (int mb = 0; mb < 8; mb++) {
#pragma unroll
            for (int hf = 0; hf < 2; hf++) {
                const float* c = accV[mb * 2 + hf];
                int m = m0 + mb * 16 + hf * 8 + ec;
                __half2 vA = __floats2half2_rn(c[0] + biasA, c[1] + biasA);
                __half2 vB = __floats2half2_rn(c[2] + biasB, c[3] + biasB);
                *(u32*)&g_vf[((size_t)b * CH + dA) * N_PIX + m] = *(const u32*)&vA;
                *(u32*)&g_vf[((size_t)b * CH + dB) * N_PIX + m] = *(const u32*)&vB;
            }
        }
    }
}

// ================== fused attention: 512 threads, 16 warps, m-tile 64 ==============
// warp (wn 0..7, wd 0..1): owns 16 queries (wn) x 128 channels (wd). E duplicated
// across wd. m-tile 64, V double-buffered 256x64, K double-buffered 64x32.
#define FA_Q    0u           // 128 x 40 halves (10240 B)
#define FA_K    10240u       // 2 x 5120 B (64 rows x 40 halves)
#define FA_KBUF 5120u
#define FA_V    20480u       // 2 x 36864 B (256 rows x 72 halves)
#define FA_VBUF 36864u
#define FA_STG  0u           // epilogue staging: 256 x 132 floats
#define FA_SROW 135168u
#define FA_SINV 135680u
#define FA_SMEM 136192u

__global__ void __launch_bounds__(512, 1) fused_attn_kernel(
    const float* __restrict__ x, float* __restrict__ out)
{
    extern __shared__ char sm[];
    const u32 S = smem_u32(sm);

    const int tid = threadIdx.x;
    const int w = tid >> 5, lane = tid & 31;
    const int wn = w & 7;            // n-group
    const int wd = w >> 3;           // d-half
    const int b  = blockIdx.z;
    const int n0 = blockIdx.x * 128;

    const __half* qf = g_qf + ((size_t)b * N_PIX + n0) * DQK;
    const __half* kf = g_kf + (size_t)b * N_PIX * DQK;
    const __half* vf = g_vf + (size_t)b * CH * N_PIX;

    auto load_q = [&]() {
        int row = tid >> 2, c = tid & 3;
        cp16(S + FA_Q + (u32)(row * 40 + c * 8) * 2, qf + (size_t)row * DQK + c * 8);
    };
    auto load_k = [&](int t2, u32 kbuf) {
        if (tid < 256) {
            int row = tid >> 2, c = tid & 3;
            cp16(kbuf + (u32)(row * 40 + c * 8) * 2,
                 kf + ((size_t)t2 * 64 + row) * DQK + c * 8);
        }
    };
    auto load_v = [&](int m0, u32 vbuf) {
#pragma unroll
        for (int j = 0; j < 4; ++j) {
            int idx = tid + j * 512;          // 0..2047
            int row = idx >> 3, c = idx & 7;
            cp16(vbuf + (u32)(row * 72 + c * 8) * 2,
                 vf + (size_t)row * N_PIX + m0 + c * 8);
        }
    };

    // ---- prologue: G1 = Q + K(0); G2 = V(0); G3 = K(1) ----
    load_q(); load_k(0, S + FA_K); CP_COMMIT();
    load_v(0, S + FA_V); CP_COMMIT();
    load_k(1, S + FA_K + FA_KBUF); CP_COMMIT();

    float accO[16][4];
#pragma unroll
    for (int i = 0; i < 16; i++)
#pragma unroll
        for (int q = 0; q < 4; q++) accO[i][q] = 0.f;
    float accRS[4] = {0.f, 0.f, 0.f, 0.f};
    float M0 = -1e30f, M1 = -1e30f;

    const int arow = wn * 16 + (lane & 15);
    const int acol = (lane >> 4) << 3;
    const int brow = (lane & 7) + ((lane >> 4) & 1) * 8;
    const int bcol = ((lane >> 3) & 1) * 8;
    const u32 ONESH2 = 0x3C003C00u;
    const float L2E = 1.4426950408889634f;

    const int NT = N_PIX / 64;   // 64 m-tiles
    for (int t = 0; t < NT; ++t) {
        CP_WAIT2();
        __syncthreads();          // K(t) visible to all warps

        // ---- E phase: 16n x 64m, fp16 (duplicated across wd) ----
        const u32 kb = S + FA_K + (u32)(t & 1) * FA_KBUF;
        float accE[8][4];
#pragma unroll
        for (int i = 0; i < 8; i++)
#pragma unroll
            for (int q = 0; q < 4; q++) accE[i][q] = 0.f;

#pragma unroll
        for (int kk = 0; kk < 32; kk += 16) {
            u32 a4[4];
            ldm4(S + FA_Q + (u32)(arow * 40 + acol + kk) * 2,
                 a4[0], a4[1], a4[2], a4[3]);
#pragma unroll
            for (int nf = 0; nf < 4; nf++) {
                u32 b0, b1, b2, b3;
                ldm4(kb + (u32)((nf * 16 + brow) * 40 + bcol + kk) * 2, b0, b1, b2, b3);
                mma16816h(accE[nf * 2],     a4, b0, b1);
                mma16816h(accE[nf * 2 + 1], a4, b2, b3);
            }
        }

        // ---- online max + guarded rescale ----
        float tm0 = -1e30f, tm1 = -1e30f;
#pragma unroll
        for (int i = 0; i < 8; i++) {
            tm0 = fmaxf(tm0, fmaxf(accE[i][0], accE[i][1]));
            tm1 = fmaxf(tm1, fmaxf(accE[i][2], accE[i][3]));
        }
        tm0 = fmaxf(tm0, __shfl_xor_sync(0xffffffffu, tm0, 1));
        tm0 = fmaxf(tm0, __shfl_xor_sync(0xffffffffu, tm0, 2));
        tm1 = fmaxf(tm1, __shfl_xor_sync(0xffffffffu, tm1, 1));
        tm1 = fmaxf(tm1, __shfl_xor_sync(0xffffffffu, tm1, 2));
        float nM0 = fmaxf(M0, tm0), nM1 = fmaxf(M1, tm1);
        if (__any_sync(0xffffffffu, (nM0 > M0) || (nM1 > M1))) {
            float sc0 = __expf(M0 - nM0), sc1 = __expf(M1 - nM1);
#pragma unroll
            for (int i = 0; i < 16; i++) {
                accO[i][0] *= sc0; accO[i][1] *= sc0;
                accO[i][2] *= sc1; accO[i][3] *= sc1;
            }
            accRS[0] *= sc0; accRS[2] *= sc1;
        }
        M0 = nM0; M1 = nM1;

        // ---- exp via ex2.approx.f16x2, P frags fp16 ----
        u32 pa[4][4];
        {
            const float zb0 = -M0 * L2E, zb1 = -M1 * L2E;
#pragma unroll
            for (int ks = 0; ks < 4; ks++) {
                float z00 = fmaf(accE[2 * ks][0], L2E, zb0);
                float z01 = fmaf(accE[2 * ks][1], L2E, zb0);
                float z02 = fmaf(accE[2 * ks][2], L2E, zb1);
                float z03 = fmaf(accE[2 * ks][3], L2E, zb1);
                float z10 = fmaf(accE[2 * ks + 1][0], L2E, zb0);
                float z11 = fmaf(accE[2 * ks + 1][1], L2E, zb0);
                float z12 = fmaf(accE[2 * ks + 1][2], L2E, zb1);
                float z13 = fmaf(accE[2 * ks + 1][3], L2E, zb1);
                __half2 h0 = __floats2half2_rn(z00, z01);
                __half2 h1 = __floats2half2_rn(z02, z03);
                __half2 h2 = __floats2half2_rn(z10, z11);
                __half2 h3 = __floats2half2_rn(z12, z13);
                pa[ks][0] = ex2h2(*(const u32*)&h0);
                pa[ks][1] = ex2h2(*(const u32*)&h1);
                pa[ks][2] = ex2h2(*(const u32*)&h2);
                pa[ks][3] = ex2h2(*(const u32*)&h3);
            }
        }
#pragma unroll
        for (int ks = 0; ks < 4; ks++)
            mma16816h(accRS, pa[ks], ONESH2, ONESH2);

        // ---- PV: warp's 128-d half over this 64-m tile ----
        CP_WAIT1();
        __syncthreads();          // V(t) visible
        {
            const u32 vb = S + FA_V + (u32)(t & 1) * FA_VBUF
                         + (u32)wd * (128u * 72u * 2u);
#pragma unroll
            for (int ks = 0; ks < 4; ks++) {
#pragma unroll
                for (int dg = 0; dg < 8; dg++) {
                    u32 boff = (u32)((dg * 16 + brow) * 72 + bcol + ks * 16) * 2;
                    u32 b0, b1, b2, b3;
                    ldm4(vb + boff, b0, b1, b2, b3);
                    mma16816h(accO[dg * 2],     pa[ks], b0, b1);
                    mma16816h(accO[dg * 2 + 1], pa[ks], b2, b3);
                }
            }
        }

        // ---- issue next loads (no sync needed: see pipeline proof) ----
        {
            int tv = (t + 1 < NT) ? t + 1 : NT - 1;
            int tk = (t + 2 < NT) ? t + 2 : NT - 1;
            load_v(tv * 64, S + FA_V + (u32)((t + 1) & 1) * FA_VBUF);
            CP_COMMIT();
            load_k(tk, S + FA_K + (u32)(t & 1) * FA_KBUF);
            CP_COMMIT();
        }
    }

    CP_WAIT0();
    __syncthreads();

    // ---- row sums -> 1/sum (wd==0 writes; values identical across wd) ----
    if (wd == 0 && (lane & 3) == 0) {
        ((float*)(sm + FA_SROW))[wn * 16 + (lane >> 2)] = accRS[0];
        ((float*)(sm + FA_SROW))[wn * 16 + (lane >> 2) + 8] = accRS[2];
    }
    __syncthreads();
    if (tid < 128)
        ((float*)(sm + FA_SINV))[tid] = 1.0f / ((float*)(sm + FA_SROW))[tid];
    __syncthreads();

    // ---- epilogue phase 1: O^T regs -> staging smem [d][n], scaled ----
    {
        float* stg = (float*)(sm + FA_STG);
        const float* sinv = (const float*)(sm + FA_SINV);
        const int er = lane >> 2;
        const int ec = 2 * (lane & 3);
        const int n = wn * 16 + er;
        const float s0 = sinv[n];
        const float s1 = sinv[n + 8];
#pragma unroll
        for (int idx = 0; idx < 16; idx++) {
            const int dg = idx >> 1, f = idx & 1;
            const int d = wd * 128 + dg * 16 + f * 8 + ec;
            stg[d * 132 + n]           = accO[idx][0] * s0;
            stg[(d + 1) * 132 + n]     = accO[idx][1] * s0;
            stg[d * 132 + n + 8]       = accO[idx][2] * s1;
            stg[(d + 1) * 132 + n + 8] = accO[idx][3] * s1;
        }
    }
    __syncthreads();

    // ---- epilogue phase 2: coalesced out = stg + x ----
    {
        const float* stg = (const float*)(sm + FA_STG);
        const int dl = tid >> 5;          // 0..15
        const int nn = (tid & 31) * 4;
#pragma unroll 4
        for (int it = 0; it < 16; it++) {
            const int d = it * 16 + dl;
            float4 v = *(const float4*)&stg[d * 132 + nn];
            size_t go = ((size_t)b * CH + d) * N_PIX + n0 + nn;
            float4 xv = *(const float4*)(x + go);
            *(float4*)(out + go) = make_float4(v.x + xv.x, v.y + xv.y,
                                               v.z + xv.z, v.w + xv.w);
        }
    }
}

// ================== launch =========================================================
extern "C" void kernel_launch(void* const* d_in, const int* in_sizes, int n_in,
                              void* d_out, int out_size)
{
    (void)in_sizes; (void)n_in; (void)out_size;
    const float* x  = (const float*)d_in[0];
    const float* Wq = (const float*)d_in[1];
    const float* bq = (const float*)d_in[2];
    const float* Wk = (const float*)d_in[3];
    const float* bk = (const float*)d_in[4];
    const float* Wv = (const float*)d_in[5];
    const float* bv = (const float*)d_in[6];
    float* out = (float*)d_out;

    static int smem_set = 0;
    if (!smem_set) {
        cudaFuncSetAttribute(fused_attn_kernel,
                             cudaFuncAttributeMaxDynamicSharedMemorySize, FA_SMEM);
        cudaFuncSetAttribute(proj_fused_kernel,
                             cudaFuncAttributeMaxDynamicSharedMemorySize, PROJ_SMEM);
        smem_set = 1;
    }

    proj_fused_kernel<<<dim3(96, 4), 256, PROJ_SMEM>>>(x, Wq, bq, Wk, bk, Wv, bv);
    fused_attn_kernel<<<dim3(32, 1, 4), 512, FA_SMEM>>>(x, out);
}

// round 16
// speedup vs baseline: 1.1656x; 1.1656x over previous
#include <cuda_runtime.h>
#include <cuda_bf16.h>
#include <cuda_fp16.h>
#include <cstdint>

#define N_PIX 4096
#define BATCH 4
#define CH    256
#define DQK   32

typedef unsigned long long u64;
typedef unsigned int u32;

// ---------------- scratch (device globals) ------------------------------------------
__device__ __half g_qf[(size_t)BATCH * N_PIX * DQK];  // Q fp16 [b][n][32]
__device__ __half g_kf[(size_t)BATCH * N_PIX * DQK];  // K fp16 [b][m][32]
__device__ __half g_vf[(size_t)BATCH * CH * N_PIX];   // V fp16 [b][d][m]

// ---------------- split-bf16 helper ---------------------------------------------------
__device__ __forceinline__ void split2(float a, float b, u32& hi, u32& lo) {
    __nv_bfloat162 h = __floats2bfloat162_rn(a, b);
    u32 hraw = *(const u32*)&h;
    float ha = __uint_as_float(hraw << 16);
    float hb = __uint_as_float(hraw & 0xFFFF0000u);
    __nv_bfloat162 l = __floats2bfloat162_rn(a - ha, b - hb);
    hi = hraw;
    lo = *(const u32*)&l;
}

// ---------------- smem / cp.async / mma helpers -------------------------------------
__device__ __forceinline__ u32 smem_u32(const void* p) {
    u32 a;
    asm("{ .reg .u64 t; cvta.to.shared.u64 t, %1; cvt.u32.u64 %0, t; }" : "=r"(a) : "l"(p));
    return a;
}
__device__ __forceinline__ void cp16(u32 d, const void* s) {
    asm volatile("cp.async.cg.shared.global [%0], [%1], 16;" :: "r"(d), "l"(s));
}
#define CP_COMMIT() asm volatile("cp.async.commit_group;" ::: "memory")
#define CP_WAIT2()  asm volatile("cp.async.wait_group 2;" ::: "memory")
#define CP_WAIT1()  asm volatile("cp.async.wait_group 1;" ::: "memory")
#define CP_WAIT0()  asm volatile("cp.async.wait_group 0;" ::: "memory")

__device__ __forceinline__ void ldm4(u32 addr, u32& r0, u32& r1, u32& r2, u32& r3) {
    asm volatile("ldmatrix.sync.aligned.m8n8.x4.shared.b16 {%0,%1,%2,%3}, [%4];"
                 : "=r"(r0), "=r"(r1), "=r"(r2), "=r"(r3) : "r"(addr));
}
__device__ __forceinline__ void ldm4t(u32 addr, u32& r0, u32& r1, u32& r2, u32& r3) {
    asm volatile("ldmatrix.sync.aligned.m8n8.x4.trans.shared.b16 {%0,%1,%2,%3}, [%4];"
                 : "=r"(r0), "=r"(r1), "=r"(r2), "=r"(r3) : "r"(addr));
}
// bf16 MMA (projections)
__device__ __forceinline__ void mma16816(float* c, const u32* a, u32 b0, u32 b1) {
    asm volatile(
        "mma.sync.aligned.m16n8k16.row.col.f32.bf16.bf16.f32 "
        "{%0,%1,%2,%3}, {%4,%5,%6,%7}, {%8,%9}, {%0,%1,%2,%3};"
        : "+f"(c[0]), "+f"(c[1]), "+f"(c[2]), "+f"(c[3])
        : "r"(a[0]), "r"(a[1]), "r"(a[2]), "r"(a[3]), "r"(b0), "r"(b1));
}
// fp16 MMA (E + PV)
__device__ __forceinline__ void mma16816h(float* c, const u32* a, u32 b0, u32 b1) {
    asm volatile(
        "mma.sync.aligned.m16n8k16.row.col.f32.f16.f16.f32 "
        "{%0,%1,%2,%3}, {%4,%5,%6,%7}, {%8,%9}, {%0,%1,%2,%3};"
        : "+f"(c[0]), "+f"(c[1]), "+f"(c[2]), "+f"(c[3])
        : "r"(a[0]), "r"(a[1]), "r"(a[2]), "r"(a[3]), "r"(b0), "r"(b1));
}
__device__ __forceinline__ u32 ex2h2(u32 z) {
    asm("ex2.approx.f16x2 %0, %0;" : "+r"(z));
    return z;
}

// ================== fat projection kernel (all tensor-core) ========================
// blockIdx.x in [0,32): q/k projection, n0 = x*128 (tensor, 64d x 128n tile)
// blockIdx.x in [32,96): V projection, d0 = ((x-32)>>5)*128, m0 = ((x-32)&31)*128
#define PROJ_SMEM 38400

__global__ void __launch_bounds__(256, 2) proj_fused_kernel(
    const float* __restrict__ x,
    const float* __restrict__ Wq, const float* __restrict__ bq,
    const float* __restrict__ Wk, const float* __restrict__ bk,
    const float* __restrict__ Wv, const float* __restrict__ bv)
{
    extern __shared__ char psm[];
    const int tid = threadIdx.x;
    const int w = tid >> 5, lane = tid & 31;
    const int b = blockIdx.y;

    // common trans-B addressing
    const int brow_c = (lane & 7) + ((lane >> 3) & 1) * 8;
    const int bcol_m = ((lane >> 4) & 1) * 8;

    if (blockIdx.x < 32) {
        // ---------------- q/k projection on tensor cores ----------------
        // Y[64 d][128 n]: rows 0..31 = q, 32..63 = k. A = stacked W (split-bf16).
        __nv_bfloat16* sWh = (__nv_bfloat16*)psm;              // 64 x 40
        __nv_bfloat16* sWl = (__nv_bfloat16*)(psm + 5120);
        __nv_bfloat16* sXh = (__nv_bfloat16*)(psm + 10240);    // 32 x 136
        __nv_bfloat16* sXl = (__nv_bfloat16*)(psm + 18944);

        const int n0 = blockIdx.x * 128;
        const int wd = w >> 1;      // 0..3 : 16 d-rows
        const int wm = w & 1;       // 0..1 : 64 n cols

        float accQ[8][4];
#pragma unroll
        for (int i = 0; i < 8; i++)
#pragma unroll
            for (int q = 0; q < 4; q++) accQ[i][q] = 0.f;

        const int arow = wd * 16 + (lane & 15);
        const int acol = (lane >> 4) << 3;
        const u32 SWH = smem_u32(sWh), SWL = smem_u32(sWl);
        const u32 SXH = smem_u32(sXh), SXL = smem_u32(sXl);

        for (int c0 = 0; c0 < CH; c0 += 32) {
            __syncthreads();
#pragma unroll
            for (int j = 0; j < 2; j++) {
                int idx = tid + j * 256;       // 0..511
                int d = idx >> 3, c4 = (idx & 7) * 4;
                const float* Wsrc = (d < 32) ? (Wq + (size_t)d * CH)
                                             : (Wk + (size_t)(d - 32) * CH);
                float4 w4 = *(const float4*)(Wsrc + c0 + c4);
                u32 h0, l0, h1, l1;
                split2(w4.x, w4.y, h0, l0);
                split2(w4.z, w4.w, h1, l1);
                *(uint2*)&sWh[d * 40 + c4] = make_uint2(h0, h1);
                *(uint2*)&sWl[d * 40 + c4] = make_uint2(l0, l1);
            }
#pragma unroll
            for (int j = 0; j < 4; j++) {
                int idx = tid + j * 256;
                int c = idx >> 5, m4 = (idx & 31) * 4;
                float4 xv4 = *(const float4*)(x + ((size_t)b * CH + c0 + c) * N_PIX + n0 + m4);
                u32 h0, l0, h1, l1;
                split2(xv4.x, xv4.y, h0, l0);
                split2(xv4.z, xv4.w, h1, l1);
                *(uint2*)&sXh[c * 136 + m4] = make_uint2(h0, h1);
                *(uint2*)&sXl[c * 136 + m4] = make_uint2(l0, l1);
            }
            __syncthreads();

#pragma unroll
            for (int kk = 0; kk < 32; kk += 16) {
                u32 ah[4], al[4];
                u32 ao = (u32)(arow * 40 + acol + kk) * 2;
                ldm4(SWH + ao, ah[0], ah[1], ah[2], ah[3]);
                ldm4(SWL + ao, al[0], al[1], al[2], al[3]);
#pragma unroll
                for (int nf = 0; nf < 4; nf++) {
                    u32 boff = (u32)((kk + brow_c) * 136 + wm * 64 + nf * 16 + bcol_m) * 2;
                    u32 bh[4], bl[4];
                    ldm4t(SXH + boff, bh[0], bh[1], bh[2], bh[3]);
                    ldm4t(SXL + boff, bl[0], bl[1], bl[2], bl[3]);
                    mma16816(accQ[nf * 2],     ah, bh[0], bh[1]);
                    mma16816(accQ[nf * 2],     ah, bl[0], bl[1]);
                    mma16816(accQ[nf * 2],     al, bh[0], bh[1]);
                    mma16816(accQ[nf * 2 + 1], ah, bh[2], bh[3]);
                    mma16816(accQ[nf * 2 + 1], ah, bl[2], bl[3]);
                    mma16816(accQ[nf * 2 + 1], al, bh[2], bh[3]);
                }
            }
        }

        // epilogue: frags (+bias) -> sY [64 d][132 n] floats, then transposed store
        __syncthreads();           // everyone done reading sW/sX
        float* sY = (float*)psm;   // 64 x 132 floats = 33792 B
        {
            const int er = lane >> 2, ec = 2 * (lane & 3);
            const int dA = wd * 16 + er;
            const int dB = dA + 8;
            const float biasA = (dA < 32) ? bq[dA] : bk[dA - 32];
            const float biasB = (dB < 32) ? bq[dB] : bk[dB - 32];
#pragma unroll
            for (int nf = 0; nf < 4; nf++) {
#pragma unroll
                for (int hf = 0; hf < 2; hf++) {
                    const float* c = accQ[nf * 2 + hf];
                    int n = wm * 64 + nf * 16 + hf * 8 + ec;
                    sY[dA * 132 + n]     = c[0] + biasA;
                    sY[dA * 132 + n + 1] = c[1] + biasA;
                    sY[dB * 132 + n]     = c[2] + biasB;
                    sY[dB * 132 + n + 1] = c[3] + biasB;
                }
            }
        }
        __syncthreads();
        {
            const int n = tid >> 1;        // 0..127
            const int half = tid & 1;      // 0 = q, 1 = k
            __half* dst = (half ? g_kf : g_qf)
                          + ((size_t)b * N_PIX + n0 + n) * DQK;
            const float* src = sY + (half * 32) * 132 + n;
#pragma unroll
            for (int d4 = 0; d4 < 8; d4++) {
                float v0 = src[(d4 * 4 + 0) * 132];
                float v1 = src[(d4 * 4 + 1) * 132];
                float v2 = src[(d4 * 4 + 2) * 132];
                float v3 = src[(d4 * 4 + 3) * 132];
                __half2 h0 = __floats2half2_rn(v0, v1);
                __half2 h1 = __floats2half2_rn(v2, v3);
                *(uint2*)(dst + d4 * 4) = make_uint2(*(const u32*)&h0, *(const u32*)&h1);
            }
        }
    } else {
        // ---------------- V projection (tensor cores, split-bf16 inputs) ----------
        __nv_bfloat16* sWh = (__nv_bfloat16*)psm;              // 128 x 40
        __nv_bfloat16* sWl = (__nv_bfloat16*)(psm + 10240);
        __nv_bfloat16* sXh = (__nv_bfloat16*)(psm + 20480);    // 32 x 136
        __nv_bfloat16* sXl = (__nv_bfloat16*)(psm + 29184);

        const int idx0 = blockIdx.x - 32;
        const int d0 = (idx0 >> 5) * 128;
        const int m0 = (idx0 & 31) * 128;

        float accV[16][4];
#pragma unroll
        for (int i = 0; i < 16; i++)
#pragma unroll
            for (int q = 0; q < 4; q++) accV[i][q] = 0.f;

        const int arow = w * 16 + (lane & 15);
        const int acol = (lane >> 4) << 3;

        const u32 SWH = smem_u32(sWh), SWL = smem_u32(sWl);
        const u32 SXH = smem_u32(sXh), SXL = smem_u32(sXl);

        for (int c0 = 0; c0 < CH; c0 += 32) {
            __syncthreads();
#pragma unroll
            for (int j = 0; j < 4; j++) {
                int idx = tid + j * 256;
                int d = idx >> 3, c4 = (idx & 7) * 4;
                float4 wv4 = *(const float4*)(Wv + (size_t)(d0 + d) * CH + c0 + c4);
                u32 h0, l0, h1, l1;
                split2(wv4.x, wv4.y, h0, l0);
                split2(wv4.z, wv4.w, h1, l1);
                *(uint2*)&sWh[d * 40 + c4] = make_uint2(h0, h1);
                *(uint2*)&sWl[d * 40 + c4] = make_uint2(l0, l1);
            }
#pragma unroll
            for (int j = 0; j < 4; j++) {
                int idx = tid + j * 256;
                int c = idx >> 5, m4 = (idx & 31) * 4;
                float4 xv4 = *(const float4*)(x + ((size_t)b * CH + c0 + c) * N_PIX + m0 + m4);
                u32 h0, l0, h1, l1;
                split2(xv4.x, xv4.y, h0, l0);
                split2(xv4.z, xv4.w, h1, l1);
                *(uint2*)&sXh[c * 136 + m4] = make_uint2(h0, h1);
                *(uint2*)&sXl[c * 136 + m4] = make_uint2(l0, l1);
            }
            __syncthreads();

#pragma unroll
            for (int kk = 0; kk < 32; kk += 16) {
                u32 ah[4], al[4];
                u32 ao = (u32)(arow * 40 + acol + kk) * 2;
                ldm4(SWH + ao, ah[0], ah[1], ah[2], ah[3]);
                ldm4(SWL + ao, al[0], al[1], al[2], al[3]);
#pragma unroll
                for (int mb = 0; mb < 8; mb++) {
                    u32 boff = (u32)((kk + brow_c) * 136 + mb * 16 + bcol_m) * 2;
                    u32 bh[4], bl[4];
                    ldm4t(SXH + boff, bh[0], bh[1], bh[2], bh[3]);
                    ldm4t(SXL + boff, bl[0], bl[1], bl[2], bl[3]);
                    mma16816(accV[mb * 2],     ah, bh[0], bh[1]);
                    mma16816(accV[mb * 2],     ah, bl[0], bl[1]);
                    mma16816(accV[mb * 2],     al, bh[0], bh[1]);
                    mma16816(accV[mb * 2 + 1], ah, bh[2], bh[3]);
                    mma16816(accV[mb * 2 + 1], ah, bl[2], bl[3]);
                    mma16816(accV[mb * 2 + 1], al, bh[2], bh[3]);
                }
            }
        }

        const int er = lane >> 2, ec = 2 * (lane & 3);
        const int dA = d0 + w * 16 + er;
        const int dB = dA + 8;
        const float biasA = bv[dA], biasB = bv[dB];
#pragma unroll
        for (int mb = 0; mb < 8; mb++) {
#pragma unroll
            for (int hf = 0; hf < 2; hf++) {
                const float* c = accV[mb * 2 + hf];
                int m = m0 + mb * 16 + hf * 8 + ec;
                __half2 vA = __floats2half2_rn(c[0] + biasA, c[1] + biasA);
                __half2 vB = __floats2half2_rn(c[2] + biasB, c[3] + biasB);
                *(u32*)&g_vf[((size_t)b * CH + dA) * N_PIX + m] = *(const u32*)&vA;
                *(u32*)&g_vf[((size_t)b * CH + dB) * N_PIX + m] = *(const u32*)&vB;
            }
        }
    }
}

// ================== fused attention: fp16 E + fp16 PV + online max (R13 base) ======
#define FA_Q    0u
#define FA_K    10240u
#define FA_KBUF 10240u
#define FA_V0   30720u
#define FA_V1   65536u
#define FA_STG  0u
#define FA_SROW 135168u
#define FA_SINV 135680u
#define FA_SMEM 136192u

__global__ void __launch_bounds__(256, 1) fused_attn_kernel(
    const float* __restrict__ x, float* __restrict__ out)
{
    extern __shared__ char sm[];
    const u32 S = smem_u32(sm);

    const int tid = threadIdx.x;
    const int w = tid >> 5, lane = tid & 31;
    const int b  = blockIdx.z;
    const int n0 = blockIdx.x * 128;

    const __half* qf = g_qf + ((size_t)b * N_PIX + n0) * DQK;
    const __half* kf = g_kf + (size_t)b * N_PIX * DQK;
    const __half* vf = g_vf + (size_t)b * CH * N_PIX;

    auto load_q = [&]() {
#pragma unroll
        for (int j = 0; j < 2; ++j) {
            int idx = tid + j * 256;
            int row = idx >> 2, c = idx & 3;
            cp16(S + FA_Q + (u32)(row * 40 + c * 8) * 2, qf + (size_t)row * DQK + c * 8);
        }
    };
    auto load_k = [&](int t2, u32 kbuf) {
#pragma unroll
        for (int j = 0; j < 2; ++j) {
            int idx = tid + j * 256;
            int row = idx >> 2, c = idx & 3;
            cp16(kbuf + (u32)(row * 40 + c * 8) * 2,
                 kf + ((size_t)t2 * 128 + row) * DQK + c * 8);
        }
    };
    auto load_v = [&](int m0, int hf) {
        const u32 vb = S + (hf ? FA_V1 : FA_V0);
#pragma unroll
        for (int j = 0; j < 8; ++j) {
            int idx = tid + j * 256;
            int row = idx >> 4, c = idx & 15;
            const __half* src = vf + ((size_t)(hf * 128 + row)) * N_PIX + m0 + c * 8;
            cp16(vb + (u32)(row * 136 + c * 8) * 2, src);
        }
    };

    // ---- prologue ----
    load_q(); load_k(0, S + FA_K); CP_COMMIT();
    load_v(0, 0); CP_COMMIT();
    load_v(0, 1); load_k(1, S + FA_K + FA_KBUF); CP_COMMIT();

    float accO[32][4];
#pragma unroll
    for (int i = 0; i < 32; i++)
#pragma unroll
        for (int q = 0; q < 4; q++) accO[i][q] = 0.f;
    float rs0 = 0.f, rs1 = 0.f;
    float M0 = -1e30f, M1 = -1e30f;

    const int arow = w * 16 + (lane & 15);
    const int acol = (lane >> 4) << 3;
    const int brow = (lane & 7) + ((lane >> 4) & 1) * 8;
    const int bcol = ((lane >> 3) & 1) * 8;
    const float L2E = 1.4426950408889634f;

    const int NT = N_PIX / 128;
    for (int t = 0; t < NT; ++t) {
        CP_WAIT2();
        __syncthreads();

        // ---- E phase: fp16 single-term ----
        const u32 kb = S + FA_K + (u32)(t & 1) * FA_KBUF;
        float accE[16][4];
#pragma unroll
        for (int i = 0; i < 16; i++)
#pragma unroll
            for (int q = 0; q < 4; q++) accE[i][q] = 0.f;

#pragma unroll
        for (int kk = 0; kk < 32; kk += 16) {
            u32 a4[4];
            u32 ao = (u32)(arow * 40 + acol + kk) * 2;
            ldm4(S + FA_Q + ao, a4[0], a4[1], a4[2], a4[3]);
#pragma unroll
            for (int nf = 0; nf < 8; nf++) {
                u32 bo = (u32)((nf * 16 + brow) * 40 + bcol + kk) * 2;
                u32 b0, b1, b2, b3;
                ldm4(kb + bo, b0, b1, b2, b3);
                mma16816h(accE[nf * 2],     a4, b0, b1);
                mma16816h(accE[nf * 2 + 1], a4, b2, b3);
            }
        }

        // ---- online max + guarded rescale ----
        float tm0 = -1e30f, tm1 = -1e30f;
#pragma unroll
        for (int i = 0; i < 16; i++) {
            tm0 = fmaxf(tm0, fmaxf(accE[i][0], accE[i][1]));
            tm1 = fmaxf(tm1, fmaxf(accE[i][2], accE[i][3]));
        }
        tm0 = fmaxf(tm0, __shfl_xor_sync(0xffffffffu, tm0, 1));
        tm0 = fmaxf(tm0, __shfl_xor_sync(0xffffffffu, tm0, 2));
        tm1 = fmaxf(tm1, __shfl_xor_sync(0xffffffffu, tm1, 1));
        tm1 = fmaxf(tm1, __shfl_xor_sync(0xffffffffu, tm1, 2));
        float nM0 = fmaxf(M0, tm0), nM1 = fmaxf(M1, tm1);
        if (__any_sync(0xffffffffu, (nM0 > M0) || (nM1 > M1))) {
            float sc0 = __expf(M0 - nM0), sc1 = __expf(M1 - nM1);
#pragma unroll
            for (int i = 0; i < 32; i++) {
                accO[i][0] *= sc0; accO[i][1] *= sc0;
                accO[i][2] *= sc1; accO[i][3] *= sc1;
            }
            rs0 *= sc0; rs1 *= sc1;
        }
        M0 = nM0; M1 = nM1;

        // ---- exp via ex2.approx.f16x2; rowsum on FMA pipe from ROUNDED P ----
        u32 pa[8][4];
        const float zb0 = -M0 * L2E, zb1 = -M1 * L2E;
#pragma unroll
        for (int ks = 0; ks < 8; ks++) {
            float z00 = fmaf(accE[2 * ks][0], L2E, zb0);
            float z01 = fmaf(accE[2 * ks][1], L2E, zb0);
            float z02 = fmaf(accE[2 * ks][2], L2E, zb1);
            float z03 = fmaf(accE[2 * ks][3], L2E, zb1);
            float z10 = fmaf(accE[2 * ks + 1][0], L2E, zb0);
            float z11 = fmaf(accE[2 * ks + 1][1], L2E, zb0);
            float z12 = fmaf(accE[2 * ks + 1][2], L2E, zb1);
            float z13 = fmaf(accE[2 * ks + 1][3], L2E, zb1);
            __half2 h0 = __floats2half2_rn(z00, z01);
            __half2 h1 = __floats2half2_rn(z02, z03);
            __half2 h2 = __floats2half2_rn(z10, z11);
            __half2 h3 = __floats2half2_rn(z12, z13);
            pa[ks][0] = ex2h2(*(const u32*)&h0);
            pa[ks][1] = ex2h2(*(const u32*)&h1);
            pa[ks][2] = ex2h2(*(const u32*)&h2);
            pa[ks][3] = ex2h2(*(const u32*)&h3);
            float2 f0 = __half22float2(*(const __half2*)&pa[ks][0]);
            float2 f1 = __half22float2(*(const __half2*)&pa[ks][1]);
            float2 f2 = __half22float2(*(const __half2*)&pa[ks][2]);
            float2 f3 = __half22float2(*(const __half2*)&pa[ks][3]);
            rs0 += (f0.x + f0.y) + (f2.x + f2.y);
            rs1 += (f1.x + f1.y) + (f3.x + f3.y);
        }

        // ---- PV half 0 (d 0..127) ----
        CP_WAIT1();
        __syncthreads();
        {
            const u32 vb = S + FA_V0;
#pragma unroll
            for (int ks = 0; ks < 8; ks++) {
#pragma unroll
                for (int dg = 0; dg < 8; dg++) {
                    u32 boff = (u32)((dg * 16 + brow) * 136 + bcol + ks * 16) * 2;
                    u32 b0, b1, b2, b3;
                    ldm4(vb + boff, b0, b1, b2, b3);
                    mma16816h(accO[dg * 2],     pa[ks], b0, b1);
                    mma16816h(accO[dg * 2 + 1], pa[ks], b2, b3);
                }
            }
        }
        __syncthreads();
        {
            int tv = (t + 1 < NT) ? t + 1 : NT - 1;
            load_v(tv * 128, 0);
            CP_COMMIT();
        }

        // ---- PV half 1 (d 128..255) ----
        CP_WAIT1();
        __syncthreads();
        {
            const u32 vb = S + FA_V1;
#pragma unroll
            for (int ks = 0; ks < 8; ks++) {
#pragma unroll
                for (int dg = 0; dg < 8; dg++) {
                    u32 boff = (u32)((dg * 16 + brow) * 136 + bcol + ks * 16) * 2;
                    u32 b0, b1, b2, b3;
                    ldm4(vb + boff, b0, b1, b2, b3);
                    mma16816h(accO[16 + dg * 2],     pa[ks], b0, b1);
                    mma16816h(accO[16 + dg * 2 + 1], pa[ks], b2, b3);
                }
            }
        }
        __syncthreads();
        {
            int tv = (t + 1 < NT) ? t + 1 : NT - 1;
            int tk = (t + 2 < NT) ? t + 2 : NT - 1;
            load_v(tv * 128, 1);
            load_k(tk, S + FA_K + (u32)(t & 1) * FA_KBUF);
            CP_COMMIT();
        }
    }

    CP_WAIT0();
    __syncthreads();

    // ---- row sums: quad-reduce, then -> 1/sum ----
    rs0 += __shfl_xor_sync(0xffffffffu, rs0, 1);
    rs0 += __shfl_xor_sync(0xffffffffu, rs0, 2);
    rs1 += __shfl_xor_sync(0xffffffffu, rs1, 1);
    rs1 += __shfl_xor_sync(0xffffffffu, rs1, 2);
    if ((lane & 3) == 0) {
        ((float*)(sm + FA_SROW))[w * 16 + (lane >> 2)] = rs0;
        ((float*)(sm + FA_SROW))[w * 16 + (lane >> 2) + 8] = rs1;
    }
    __syncthreads();
    if (tid < 128)
        ((float*)(sm + FA_SINV))[tid] = 1.0f / ((float*)(sm + FA_SROW))[tid];
    __syncthreads();

    // ---- epilogue phase 1: O^T regs -> staging smem [d][n], scaled by rinv[n] ----
    {
        float* stg = (float*)(sm + FA_STG);
        const float* sinv = (const float*)(sm + FA_SINV);
        const int er = lane >> 2;
        const int ec = 2 * (lane & 3);
        const int n = w * 16 + er;
        const float s0 = sinv[n];
        const float s1 = sinv[n + 8];
#pragma unroll
        for (int idx = 0; idx < 32; idx++) {
            const int hf = idx >> 4, rem = idx & 15;
            const int dg = rem >> 1, f = rem & 1;
            const int d = hf * 128 + dg * 16 + f * 8 + ec;
            stg[d * 132 + n]           = accO[idx][0] * s0;
            stg[(d + 1) * 132 + n]     = accO[idx][1] * s0;
            stg[d * 132 + n + 8]       = accO[idx][2] * s1;
            stg[(d + 1) * 132 + n + 8] = accO[idx][3] * s1;
        }
    }
    __syncthreads();

    // ---- epilogue phase 2: coalesced out = stg + x ----
    {
        const float* stg = (const float*)(sm + FA_STG);
        const int dl = tid >> 5;
        const int nn = (tid & 31) * 4;
#pragma unroll 4
        for (int it = 0; it < 32; it++) {
            const int d = it * 8 + dl;
            float4 v = *(const float4*)&stg[d * 132 + nn];
            size_t go = ((size_t)b * CH + d) * N_PIX + n0 + nn;
            float4 xv = *(const float4*)(x + go);
            *(float4*)(out + go) = make_float4(v.x + xv.x, v.y + xv.y,
                                               v.z + xv.z, v.w + xv.w);
        }
    }
}

// ================== launch =========================================================
extern "C" void kernel_launch(void* const* d_in, const int* in_sizes, int n_in,
                              void* d_out, int out_size)
{
    (void)in_sizes; (void)n_in; (void)out_size;
    const float* x  = (const float*)d_in[0];
    const float* Wq = (const float*)d_in[1];
    const float* bq = (const float*)d_in[2];
    const float* Wk = (const float*)d_in[3];
    const float* bk = (const float*)d_in[4];
    const float* Wv = (const float*)d_in[5];
    const float* bv = (const float*)d_in[6];
    float* out = (float*)d_out;

    static int smem_set = 0;
    if (!smem_set) {
        cudaFuncSetAttribute(fused_attn_kernel,
                             cudaFuncAttributeMaxDynamicSharedMemorySize, FA_SMEM);
        cudaFuncSetAttribute(proj_fused_kernel,
                             cudaFuncAttributeMaxDynamicSharedMemorySize, PROJ_SMEM);
        smem_set = 1;
    }

    proj_fused_kernel<<<dim3(96, 4), 256, PROJ_SMEM>>>(x, Wq, bq, Wk, bk, Wv, bv);
    fused_attn_kernel<<<dim3(32, 1, 4), 256, FA_SMEM>>>(x, out);
}

// round 17
// speedup vs baseline: 1.2478x; 1.0705x over previous
#include <cuda_runtime.h>
#include <cuda_bf16.h>
#include <cuda_fp16.h>
#include <cstdint>

#define N_PIX 4096
#define BATCH 4
#define CH    256
#define DQK   32

typedef unsigned long long u64;
typedef unsigned int u32;

// ---------------- scratch (device globals) ------------------------------------------
__device__ __half g_qf[(size_t)BATCH * N_PIX * DQK];  // Q fp16 [b][n][32]
__device__ __half g_kf[(size_t)BATCH * N_PIX * DQK];  // K fp16 [b][m][32]
__device__ __half g_vf[(size_t)BATCH * CH * N_PIX];   // V fp16 [b][d][m]

// ---------------- smem / cp.async / mma helpers -------------------------------------
__device__ __forceinline__ u32 smem_u32(const void* p) {
    u32 a;
    asm("{ .reg .u64 t; cvta.to.shared.u64 t, %1; cvt.u32.u64 %0, t; }" : "=r"(a) : "l"(p));
    return a;
}
__device__ __forceinline__ void cp16(u32 d, const void* s) {
    asm volatile("cp.async.cg.shared.global [%0], [%1], 16;" :: "r"(d), "l"(s));
}
#define CP_COMMIT() asm volatile("cp.async.commit_group;" ::: "memory")
#define CP_WAIT2()  asm volatile("cp.async.wait_group 2;" ::: "memory")
#define CP_WAIT1()  asm volatile("cp.async.wait_group 1;" ::: "memory")
#define CP_WAIT0()  asm volatile("cp.async.wait_group 0;" ::: "memory")

__device__ __forceinline__ void ldm4(u32 addr, u32& r0, u32& r1, u32& r2, u32& r3) {
    asm volatile("ldmatrix.sync.aligned.m8n8.x4.shared.b16 {%0,%1,%2,%3}, [%4];"
                 : "=r"(r0), "=r"(r1), "=r"(r2), "=r"(r3) : "r"(addr));
}
__device__ __forceinline__ void ldm4t(u32 addr, u32& r0, u32& r1, u32& r2, u32& r3) {
    asm volatile("ldmatrix.sync.aligned.m8n8.x4.trans.shared.b16 {%0,%1,%2,%3}, [%4];"
                 : "=r"(r0), "=r"(r1), "=r"(r2), "=r"(r3) : "r"(addr));
}
// fp16 MMA (everything)
__device__ __forceinline__ void mma16816h(float* c, const u32* a, u32 b0, u32 b1) {
    asm volatile(
        "mma.sync.aligned.m16n8k16.row.col.f32.f16.f16.f32 "
        "{%0,%1,%2,%3}, {%4,%5,%6,%7}, {%8,%9}, {%0,%1,%2,%3};"
        : "+f"(c[0]), "+f"(c[1]), "+f"(c[2]), "+f"(c[3])
        : "r"(a[0]), "r"(a[1]), "r"(a[2]), "r"(a[3]), "r"(b0), "r"(b1));
}
__device__ __forceinline__ u32 ex2h2(u32 z) {
    asm("ex2.approx.f16x2 %0, %0;" : "+r"(z));
    return z;
}
__device__ __forceinline__ u32 h2pack(float a, float b) {
    __half2 h = __floats2half2_rn(a, b);
    return *(const u32*)&h;
}

// ================== fat projection kernel (single-fp16 tensor-core) ================
// blockIdx.x in [0,32): q/k projection, n0 = x*128 (64d x 128n tile)
// blockIdx.x in [32,96): V projection, d0 = ((x-32)>>5)*128, m0 = ((x-32)&31)*128
#define PROJ_SMEM 38400

__global__ void __launch_bounds__(256, 2) proj_fused_kernel(
    const float* __restrict__ x,
    const float* __restrict__ Wq, const float* __restrict__ bq,
    const float* __restrict__ Wk, const float* __restrict__ bk,
    const float* __restrict__ Wv, const float* __restrict__ bv)
{
    extern __shared__ char psm[];
    const int tid = threadIdx.x;
    const int w = tid >> 5, lane = tid & 31;
    const int b = blockIdx.y;

    // common trans-B addressing
    const int brow_c = (lane & 7) + ((lane >> 3) & 1) * 8;
    const int bcol_m = ((lane >> 4) & 1) * 8;

    if (blockIdx.x < 32) {
        // ---------------- q/k projection (fp16 tensor) ----------------
        __half* sWf = (__half*)psm;              // 64 x 40 (5120 B)
        __half* sXf = (__half*)(psm + 5120);     // 32 x 136 (8704 B)

        const int n0 = blockIdx.x * 128;
        const int wd = w >> 1;      // 0..3 : 16 d-rows
        const int wm = w & 1;       // 0..1 : 64 n cols

        float accQ[8][4];
#pragma unroll
        for (int i = 0; i < 8; i++)
#pragma unroll
            for (int q = 0; q < 4; q++) accQ[i][q] = 0.f;

        const int arow = wd * 16 + (lane & 15);
        const int acol = (lane >> 4) << 3;
        const u32 SWF = smem_u32(sWf), SXF = smem_u32(sXf);

        for (int c0 = 0; c0 < CH; c0 += 32) {
            __syncthreads();
#pragma unroll
            for (int j = 0; j < 2; j++) {
                int idx = tid + j * 256;       // 0..511
                int d = idx >> 3, c4 = (idx & 7) * 4;
                const float* Wsrc = (d < 32) ? (Wq + (size_t)d * CH)
                                             : (Wk + (size_t)(d - 32) * CH);
                float4 w4 = *(const float4*)(Wsrc + c0 + c4);
                *(uint2*)&sWf[d * 40 + c4] =
                    make_uint2(h2pack(w4.x, w4.y), h2pack(w4.z, w4.w));
            }
#pragma unroll
            for (int j = 0; j < 4; j++) {
                int idx = tid + j * 256;
                int c = idx >> 5, m4 = (idx & 31) * 4;
                float4 xv4 = *(const float4*)(x + ((size_t)b * CH + c0 + c) * N_PIX + n0 + m4);
                *(uint2*)&sXf[c * 136 + m4] =
                    make_uint2(h2pack(xv4.x, xv4.y), h2pack(xv4.z, xv4.w));
            }
            __syncthreads();

#pragma unroll
            for (int kk = 0; kk < 32; kk += 16) {
                u32 a4[4];
                ldm4(SWF + (u32)(arow * 40 + acol + kk) * 2, a4[0], a4[1], a4[2], a4[3]);
#pragma unroll
                for (int nf = 0; nf < 4; nf++) {
                    u32 boff = (u32)((kk + brow_c) * 136 + wm * 64 + nf * 16 + bcol_m) * 2;
                    u32 b0, b1, b2, b3;
                    ldm4t(SXF + boff, b0, b1, b2, b3);
                    mma16816h(accQ[nf * 2],     a4, b0, b1);
                    mma16816h(accQ[nf * 2 + 1], a4, b2, b3);
                }
            }
        }

        // epilogue: frags (+bias) -> sY [64 d][132 n] floats, then transposed store
        __syncthreads();
        float* sY = (float*)psm;   // 64 x 132 floats = 33792 B
        {
            const int er = lane >> 2, ec = 2 * (lane & 3);
            const int dA = wd * 16 + er;
            const int dB = dA + 8;
            const float biasA = (dA < 32) ? bq[dA] : bk[dA - 32];
            const float biasB = (dB < 32) ? bq[dB] : bk[dB - 32];
#pragma unroll
            for (int nf = 0; nf < 4; nf++) {
#pragma unroll
                for (int hf = 0; hf < 2; hf++) {
                    const float* c = accQ[nf * 2 + hf];
                    int n = wm * 64 + nf * 16 + hf * 8 + ec;
                    sY[dA * 132 + n]     = c[0] + biasA;
                    sY[dA * 132 + n + 1] = c[1] + biasA;
                    sY[dB * 132 + n]     = c[2] + biasB;
                    sY[dB * 132 + n + 1] = c[3] + biasB;
                }
            }
        }
        __syncthreads();
        {
            const int n = tid >> 1;        // 0..127
            const int half = tid & 1;      // 0 = q, 1 = k
            __half* dst = (half ? g_kf : g_qf)
                          + ((size_t)b * N_PIX + n0 + n) * DQK;
            const float* src = sY + (half * 32) * 132 + n;
#pragma unroll
            for (int d4 = 0; d4 < 8; d4++) {
                float v0 = src[(d4 * 4 + 0) * 132];
                float v1 = src[(d4 * 4 + 1) * 132];
                float v2 = src[(d4 * 4 + 2) * 132];
                float v3 = src[(d4 * 4 + 3) * 132];
                *(uint2*)(dst + d4 * 4) = make_uint2(h2pack(v0, v1), h2pack(v2, v3));
            }
        }
    } else {
        // ---------------- V projection (fp16 tensor) ----------------
        __half* sWf = (__half*)psm;              // 128 x 40 (10240 B)
        __half* sXf = (__half*)(psm + 10240);    // 32 x 136 (8704 B)

        const int idx0 = blockIdx.x - 32;
        const int d0 = (idx0 >> 5) * 128;
        const int m0 = (idx0 & 31) * 128;

        float accV[16][4];
#pragma unroll
        for (int i = 0; i < 16; i++)
#pragma unroll
            for (int q = 0; q < 4; q++) accV[i][q] = 0.f;

        const int arow = w * 16 + (lane & 15);
        const int acol = (lane >> 4) << 3;
        const u32 SWF = smem_u32(sWf), SXF = smem_u32(sXf);

        for (int c0 = 0; c0 < CH; c0 += 32) {
            __syncthreads();
#pragma unroll
            for (int j = 0; j < 4; j++) {
                int idx = tid + j * 256;
                int d = idx >> 3, c4 = (idx & 7) * 4;
                float4 wv4 = *(const float4*)(Wv + (size_t)(d0 + d) * CH + c0 + c4);
                *(uint2*)&sWf[d * 40 + c4] =
                    make_uint2(h2pack(wv4.x, wv4.y), h2pack(wv4.z, wv4.w));
            }
#pragma unroll
            for (int j = 0; j < 4; j++) {
                int idx = tid + j * 256;
                int c = idx >> 5, m4 = (idx & 31) * 4;
                float4 xv4 = *(const float4*)(x + ((size_t)b * CH + c0 + c) * N_PIX + m0 + m4);
                *(uint2*)&sXf[c * 136 + m4] =
                    make_uint2(h2pack(xv4.x, xv4.y), h2pack(xv4.z, xv4.w));
            }
            __syncthreads();

#pragma unroll
            for (int kk = 0; kk < 32; kk += 16) {
                u32 a4[4];
                ldm4(SWF + (u32)(arow * 40 + acol + kk) * 2, a4[0], a4[1], a4[2], a4[3]);
#pragma unroll
                for (int mb = 0; mb < 8; mb++) {
                    u32 boff = (u32)((kk + brow_c) * 136 + mb * 16 + bcol_m) * 2;
                    u32 b0, b1, b2, b3;
                    ldm4t(SXF + boff, b0, b1, b2, b3);
                    mma16816h(accV[mb * 2],     a4, b0, b1);
                    mma16816h(accV[mb * 2 + 1], a4, b2, b3);
                }
            }
        }

        const int er = lane >> 2, ec = 2 * (lane & 3);
        const int dA = d0 + w * 16 + er;
        const int dB = dA + 8;
        const float biasA = bv[dA], biasB = bv[dB];
#pragma unroll
        for (int mb = 0; mb < 8; mb++) {
#pragma unroll
            for (int hf = 0; hf < 2; hf++) {
                const float* c = accV[mb * 2 + hf];
                int m = m0 + mb * 16 + hf * 8 + ec;
                *(u32*)&g_vf[((size_t)b * CH + dA) * N_PIX + m] = h2pack(c[0] + biasA, c[1] + biasA);
                *(u32*)&g_vf[((size_t)b * CH + dB) * N_PIX + m] = h2pack(c[2] + biasB, c[3] + biasB);
            }
        }
    }
}

// ================== fused attention: fp16 E + fp16 PV + online max (R13) ===========
#define FA_Q    0u
#define FA_K    10240u
#define FA_KBUF 10240u
#define FA_V0   30720u
#define FA_V1   65536u
#define FA_STG  0u
#define FA_SROW 135168u
#define FA_SINV 135680u
#define FA_SMEM 136192u

__global__ void __launch_bounds__(256, 1) fused_attn_kernel(
    const float* __restrict__ x, float* __restrict__ out)
{
    extern __shared__ char sm[];
    const u32 S = smem_u32(sm);

    const int tid = threadIdx.x;
    const int w = tid >> 5, lane = tid & 31;
    const int b  = blockIdx.z;
    const int n0 = blockIdx.x * 128;

    const __half* qf = g_qf + ((size_t)b * N_PIX + n0) * DQK;
    const __half* kf = g_kf + (size_t)b * N_PIX * DQK;
    const __half* vf = g_vf + (size_t)b * CH * N_PIX;

    auto load_q = [&]() {
#pragma unroll
        for (int j = 0; j < 2; ++j) {
            int idx = tid + j * 256;
            int row = idx >> 2, c = idx & 3;
            cp16(S + FA_Q + (u32)(row * 40 + c * 8) * 2, qf + (size_t)row * DQK + c * 8);
        }
    };
    auto load_k = [&](int t2, u32 kbuf) {
#pragma unroll
        for (int j = 0; j < 2; ++j) {
            int idx = tid + j * 256;
            int row = idx >> 2, c = idx & 3;
            cp16(kbuf + (u32)(row * 40 + c * 8) * 2,
                 kf + ((size_t)t2 * 128 + row) * DQK + c * 8);
        }
    };
    auto load_v = [&](int m0, int hf) {
        const u32 vb = S + (hf ? FA_V1 : FA_V0);
#pragma unroll
        for (int j = 0; j < 8; ++j) {
            int idx = tid + j * 256;
            int row = idx >> 4, c = idx & 15;
            const __half* src = vf + ((size_t)(hf * 128 + row)) * N_PIX + m0 + c * 8;
            cp16(vb + (u32)(row * 136 + c * 8) * 2, src);
        }
    };

    // ---- prologue ----
    load_q(); load_k(0, S + FA_K); CP_COMMIT();
    load_v(0, 0); CP_COMMIT();
    load_v(0, 1); load_k(1, S + FA_K + FA_KBUF); CP_COMMIT();

    float accO[32][4];
#pragma unroll
    for (int i = 0; i < 32; i++)
#pragma unroll
        for (int q = 0; q < 4; q++) accO[i][q] = 0.f;
    float accRS[4] = {0.f, 0.f, 0.f, 0.f};
    float M0 = -1e30f, M1 = -1e30f;

    const int arow = w * 16 + (lane & 15);
    const int acol = (lane >> 4) << 3;
    const int brow = (lane & 7) + ((lane >> 4) & 1) * 8;
    const int bcol = ((lane >> 3) & 1) * 8;
    const u32 ONESH2 = 0x3C003C00u;
    const float L2E = 1.4426950408889634f;

    const int NT = N_PIX / 128;
    for (int t = 0; t < NT; ++t) {
        CP_WAIT2();
        __syncthreads();

        // ---- E phase: fp16 single-term ----
        const u32 kb = S + FA_K + (u32)(t & 1) * FA_KBUF;
        float accE[16][4];
#pragma unroll
        for (int i = 0; i < 16; i++)
#pragma unroll
            for (int q = 0; q < 4; q++) accE[i][q] = 0.f;

#pragma unroll
        for (int kk = 0; kk < 32; kk += 16) {
            u32 a4[4];
            u32 ao = (u32)(arow * 40 + acol + kk) * 2;
            ldm4(S + FA_Q + ao, a4[0], a4[1], a4[2], a4[3]);
#pragma unroll
            for (int nf = 0; nf < 8; nf++) {
                u32 bo = (u32)((nf * 16 + brow) * 40 + bcol + kk) * 2;
                u32 b0, b1, b2, b3;
                ldm4(kb + bo, b0, b1, b2, b3);
                mma16816h(accE[nf * 2],     a4, b0, b1);
                mma16816h(accE[nf * 2 + 1], a4, b2, b3);
            }
        }

        // ---- online max + guarded rescale ----
        float tm0 = -1e30f, tm1 = -1e30f;
#pragma unroll
        for (int i = 0; i < 16; i++) {
            tm0 = fmaxf(tm0, fmaxf(accE[i][0], accE[i][1]));
            tm1 = fmaxf(tm1, fmaxf(accE[i][2], accE[i][3]));
        }
        tm0 = fmaxf(tm0, __shfl_xor_sync(0xffffffffu, tm0, 1));
        tm0 = fmaxf(tm0, __shfl_xor_sync(0xffffffffu, tm0, 2));
        tm1 = fmaxf(tm1, __shfl_xor_sync(0xffffffffu, tm1, 1));
        tm1 = fmaxf(tm1, __shfl_xor_sync(0xffffffffu, tm1, 2));
        float nM0 = fmaxf(M0, tm0), nM1 = fmaxf(M1, tm1);
        if (__any_sync(0xffffffffu, (nM0 > M0) || (nM1 > M1))) {
            float sc0 = __expf(M0 - nM0), sc1 = __expf(M1 - nM1);
#pragma unroll
            for (int i = 0; i < 32; i++) {
                accO[i][0] *= sc0; accO[i][1] *= sc0;
                accO[i][2] *= sc1; accO[i][3] *= sc1;
            }
            accRS[0] *= sc0; accRS[2] *= sc1;
        }
        M0 = nM0; M1 = nM1;

        // ---- exp via ex2.approx.f16x2, P frags fp16; rowsum via ones-MMA ----
        u32 pa[8][4];
        const float zb0 = -M0 * L2E, zb1 = -M1 * L2E;
#pragma unroll
        for (int ks = 0; ks < 8; ks++) {
            float z00 = fmaf(accE[2 * ks][0], L2E, zb0);
            float z01 = fmaf(accE[2 * ks][1], L2E, zb0);
            float z02 = fmaf(accE[2 * ks][2], L2E, zb1);
            float z03 = fmaf(accE[2 * ks][3], L2E, zb1);
            float z10 = fmaf(accE[2 * ks + 1][0], L2E, zb0);
            float z11 = fmaf(accE[2 * ks + 1][1], L2E, zb0);
            float z12 = fmaf(accE[2 * ks + 1][2], L2E, zb1);
            float z13 = fmaf(accE[2 * ks + 1][3], L2E, zb1);
            pa[ks][0] = ex2h2(h2pack(z00, z01));
            pa[ks][1] = ex2h2(h2pack(z02, z03));
            pa[ks][2] = ex2h2(h2pack(z10, z11));
            pa[ks][3] = ex2h2(h2pack(z12, z13));
        }
#pragma unroll
        for (int ks = 0; ks < 8; ks++)
            mma16816h(accRS, pa[ks], ONESH2, ONESH2);

        // ---- PV half 0 (d 0..127) ----
        CP_WAIT1();
        __syncthreads();
        {
            const u32 vb = S + FA_V0;
#pragma unroll
            for (int ks = 0; ks < 8; ks++) {
#pragma unroll
                for (int dg = 0; dg < 8; dg++) {
                    u32 boff = (u32)((dg * 16 + brow) * 136 + bcol + ks * 16) * 2;
                    u32 b0, b1, b2, b3;
                    ldm4(vb + boff, b0, b1, b2, b3);
                    mma16816h(accO[dg * 2],     pa[ks], b0, b1);
                    mma16816h(accO[dg * 2 + 1], pa[ks], b2, b3);
                }
            }
        }
        __syncthreads();
        {
            int tv = (t + 1 < NT) ? t + 1 : NT - 1;
            load_v(tv * 128, 0);
            CP_COMMIT();
        }

        // ---- PV half 1 (d 128..255) ----
        CP_WAIT1();
        __syncthreads();
        {
            const u32 vb = S + FA_V1;
#pragma unroll
            for (int ks = 0; ks < 8; ks++) {
#pragma unroll
                for (int dg = 0; dg < 8; dg++) {
                    u32 boff = (u32)((dg * 16 + brow) * 136 + bcol + ks * 16) * 2;
                    u32 b0, b1, b2, b3;
                    ldm4(vb + boff, b0, b1, b2, b3);
                    mma16816h(accO[16 + dg * 2],     pa[ks], b0, b1);
                    mma16816h(accO[16 + dg * 2 + 1], pa[ks], b2, b3);
                }
            }
        }
        __syncthreads();
        {
            int tv = (t + 1 < NT) ? t + 1 : NT - 1;
            int tk = (t + 2 < NT) ? t + 2 : NT - 1;
            load_v(tv * 128, 1);
            load_k(tk, S + FA_K + (u32)(t & 1) * FA_KBUF);
            CP_COMMIT();
        }
    }

    CP_WAIT0();
    __syncthreads();

    // ---- row sums -> 1/sum (accRS quad-identical) ----
    if ((lane & 3) == 0) {
        ((float*)(sm + FA_SROW))[w * 16 + (lane >> 2)] = accRS[0];
        ((float*)(sm + FA_SROW))[w * 16 + (lane >> 2) + 8] = accRS[2];
    }
    __syncthreads();
    if (tid < 128)
        ((float*)(sm + FA_SINV))[tid] = 1.0f / ((float*)(sm + FA_SROW))[tid];
    __syncthreads();

    // ---- epilogue phase 1: O^T regs -> staging smem [d][n], scaled by rinv[n] ----
    {
        float* stg = (float*)(sm + FA_STG);
        const float* sinv = (const float*)(sm + FA_SINV);
        const int er = lane >> 2;
        const int ec = 2 * (lane & 3);
        const int n = w * 16 + er;
        const float s0 = sinv[n];
        const float s1 = sinv[n + 8];
#pragma unroll
        for (int idx = 0; idx < 32; idx++) {
            const int hf = idx >> 4, rem = idx & 15;
            const int dg = rem >> 1, f = rem & 1;
            const int d = hf * 128 + dg * 16 + f * 8 + ec;
            stg[d * 132 + n]           = accO[idx][0] * s0;
            stg[(d + 1) * 132 + n]     = accO[idx][1] * s0;
            stg[d * 132 + n + 8]       = accO[idx][2] * s1;
            stg[(d + 1) * 132 + n + 8] = accO[idx][3] * s1;
        }
    }
    __syncthreads();

    // ---- epilogue phase 2: coalesced out = stg + x ----
    {
        const float* stg = (const float*)(sm + FA_STG);
        const int dl = tid >> 5;
        const int nn = (tid & 31) * 4;
#pragma unroll 4
        for (int it = 0; it < 32; it++) {
            const int d = it * 8 + dl;
            float4 v = *(const float4*)&stg[d * 132 + nn];
            size_t go = ((size_t)b * CH + d) * N_PIX + n0 + nn;
            float4 xv = *(const float4*)(x + go);
            *(float4*)(out + go) = make_float4(v.x + xv.x, v.y + xv.y,
                                               v.z + xv.z, v.w + xv.w);
        }
    }
}

// ================== launch =========================================================
extern "C" void kernel_launch(void* const* d_in, const int* in_sizes, int n_in,
                              void* d_out, int out_size)
{
    (void)in_sizes; (void)n_in; (void)out_size;
    const float* x  = (const float*)d_in[0];
    const float* Wq = (const float*)d_in[1];
    const float* bq = (const float*)d_in[2];
    const float* Wk = (const float*)d_in[3];
    const float* bk = (const float*)d_in[4];
    const float* Wv = (const float*)d_in[5];
    const float* bv = (const float*)d_in[6];
    float* out = (float*)d_out;

    static int smem_set = 0;
    if (!smem_set) {
        cudaFuncSetAttribute(fused_attn_kernel,
                             cudaFuncAttributeMaxDynamicSharedMemorySize, FA_SMEM);
        cudaFuncSetAttribute(proj_fused_kernel,
                             cudaFuncAttributeMaxDynamicSharedMemorySize, PROJ_SMEM);
        smem_set = 1;
    }

    proj_fused_kernel<<<dim3(96, 4), 256, PROJ_SMEM>>>(x, Wq, bq, Wk, bk, Wv, bv);
    fused_attn_kernel<<<dim3(32, 1, 4), 256, FA_SMEM>>>(x, out);
}